// round 9
// baseline (speedup 1.0000x reference)
#include <cuda_runtime.h>
#include <cuda_bf16.h>
#include <stdint.h>

// LUT_82085414961764: out = a[idx]*d + b[idx], idx = searchsorted(x, d, 'left')
// R8 = R7 resubmitted (R7 bench was an infra failure, kernel never ran):
// NB=16384 bins (halves scan fraction), fminf/fmaxf clamp, 4 CTAs/SM.
//   - x_s[1025]          : breakpoints + +inf sentinel (scan fallback)
//   - ab_s[1025] float2  : interleaved (a,b), single LDS.64 gather
//   - bins_s[16384] u16  : {start index (15b) | has-breakpoints flag (1b)}
// Bin function g() is the IDENTICAL monotone float expression at build and
// query time, so `start` is a provably correct lower bound for the scan.

#define KMAX 1024
#define NB   16384

__global__ __launch_bounds__(512, 4)
void lut_kernel(const float* __restrict__ data,
                const float* __restrict__ x,
                const float* __restrict__ a,
                const float* __restrict__ b,
                float* __restrict__ out,
                int K, long long n)
{
    __shared__ float    x_s[KMAX + 1];
    __shared__ float2   ab_s[KMAX + 1];
    __shared__ uint16_t bins_s[NB];

    const int tid = threadIdx.x;
    const int bd  = blockDim.x;

    // ---- build phase ----------------------------------------------------
    for (int i = tid; i < K; i += bd)  x_s[i] = x[i];
    for (int i = tid; i <= K; i += bd) ab_s[i] = make_float2(a[i], b[i]);
    if (tid == 0) x_s[K] = __int_as_float(0x7F800000);  // +inf sentinel
    __syncthreads();

    const float LO    = x_s[0];
    const float span  = x_s[K - 1] - LO;
    const float scale = (span > 0.0f) ? ((float)NB / span) : 0.0f;
    const float NBm1  = (float)(NB - 1);

    // monotone bin function — identical expression at build and query
    auto g = [&](float v) -> int {
        float t = (v - LO) * scale;
        t = fminf(fmaxf(t, 0.0f), NBm1);
        return (int)t;
    };

    // bins_s[bin] = (first i with g(x_s[i]) >= bin) | (flag<<15)
    for (int bin = tid; bin < NB; bin += bd) {
        int lo = 0, hi = K;
        while (lo < hi) {
            int mid = (lo + hi) >> 1;
            if (g(x_s[mid]) < bin) lo = mid + 1; else hi = mid;
        }
        unsigned flag = (lo < K && g(x_s[lo]) == bin) ? 0x8000u : 0u;
        bins_s[bin] = (uint16_t)((unsigned)lo | flag);
    }
    __syncthreads();

    // ---- streaming phase -------------------------------------------------
    auto lut1 = [&](float d) -> float {
        float t = (d - LO) * scale;
        t = fminf(fmaxf(t, 0.0f), NBm1);
        int bin = (int)t;
        unsigned v = bins_s[bin];
        int idx = (int)(v & 0x7FFFu);
        if (v & 0x8000u) {
            // forward scan; x_s[K] = +inf terminates without a bounds check
            while (x_s[idx] < d) ++idx;
        }
        float2 ab = ab_s[idx];
        return fmaf(ab.x, d, ab.y);
    };

    const long long n4 = n >> 2;
    const float4* __restrict__ in4  = (const float4*)data;
    float4* __restrict__       out4 = (float4*)out;
    const long long stride = (long long)gridDim.x * bd;

    for (long long i = (long long)blockIdx.x * bd + tid; i < n4; i += stride) {
        float4 v = in4[i];
        float4 r;
        r.x = lut1(v.x);
        r.y = lut1(v.y);
        r.z = lut1(v.z);
        r.w = lut1(v.w);
        out4[i] = r;
    }

    // tail (n not divisible by 4)
    for (long long i = (n4 << 2) + (long long)blockIdx.x * bd + tid; i < n;
         i += stride) {
        out[i] = lut1(data[i]);
    }
}

extern "C" void kernel_launch(void* const* d_in, const int* in_sizes, int n_in,
                              void* d_out, int out_size)
{
    const float* data = (const float*)d_in[0];
    const float* x    = (const float*)d_in[1];
    const float* a    = (const float*)d_in[2];
    const float* b    = (const float*)d_in[3];
    float* out        = (float*)d_out;

    int K = in_sizes[1];
    if (K > KMAX) K = KMAX;  // problem constant is 1024
    long long n = (long long)out_size;

    const int threads = 512;
    int blocks = 608;  // 4 CTAs per SM on 152 SMs
    long long need = (n / 4 + threads - 1) / threads;
    if ((long long)blocks > need && need > 0) blocks = (int)need;
    if (blocks < 1) blocks = 1;

    lut_kernel<<<blocks, threads>>>(data, x, a, b, out, K, n);
}

// round 10
// speedup vs baseline: 1.1076x; 1.1076x over previous
#include <cuda_runtime.h>
#include <cuda_bf16.h>
#include <stdint.h>

// LUT_82085414961764: out = a[idx]*d + b[idx], idx = searchsorted(x, d, 'left')
// R9: R6 table (NB=8192, branchy clamp — best known) + batch-of-8 ILP
// stream loop (stage-structured so 8 independent LDS chains are in flight),
// 3 CTAs/SM x 512 threads (regs ~40).
//   - x_s[1025]          : breakpoints + +inf sentinel (scan fallback)
//   - ab_s[1025] float2  : interleaved (a,b), single LDS.64 gather
//   - bins_s[8192] u16   : {start index (15b) | has-breakpoints flag (1b)}
// Bin function g() is the IDENTICAL monotone float expression at build and
// query time, so `start` is a provably correct lower bound for the scan.

#define KMAX 1024
#define NB   8192

__global__ __launch_bounds__(512, 3)
void lut_kernel(const float* __restrict__ data,
                const float* __restrict__ x,
                const float* __restrict__ a,
                const float* __restrict__ b,
                float* __restrict__ out,
                int K, long long n)
{
    __shared__ float    x_s[KMAX + 1];
    __shared__ float2   ab_s[KMAX + 1];
    __shared__ uint16_t bins_s[NB];

    const int tid = threadIdx.x;
    const int bd  = blockDim.x;

    // ---- build phase ----------------------------------------------------
    for (int i = tid; i < K; i += bd)  x_s[i] = x[i];
    for (int i = tid; i <= K; i += bd) ab_s[i] = make_float2(a[i], b[i]);
    if (tid == 0) x_s[K] = __int_as_float(0x7F800000);  // +inf sentinel
    __syncthreads();

    const float LO    = x_s[0];
    const float span  = x_s[K - 1] - LO;
    const float scale = (span > 0.0f) ? ((float)NB / span) : 0.0f;
    const float NBf   = (float)NB;

    // monotone bin function — identical expression at build and query
    auto g = [&](float v) -> int {
        float t = (v - LO) * scale;
        if (t < 0.0f) return 0;
        if (t >= NBf) return NB - 1;
        return (int)t;
    };

    // bins_s[bin] = (first i with g(x_s[i]) >= bin) | (flag<<15)
    for (int bin = tid; bin < NB; bin += bd) {
        int lo = 0, hi = K;
        while (lo < hi) {
            int mid = (lo + hi) >> 1;
            if (g(x_s[mid]) < bin) lo = mid + 1; else hi = mid;
        }
        unsigned flag = (lo < K && g(x_s[lo]) == bin) ? 0x8000u : 0u;
        bins_s[bin] = (uint16_t)((unsigned)lo | flag);
    }
    __syncthreads();

    // single-element path (tails / odd iterations)
    auto lut1 = [&](float d) -> float {
        float t = (d - LO) * scale;
        int bin;
        if (t < 0.0f)      bin = 0;
        else if (t >= NBf) bin = NB - 1;
        else               bin = (int)t;
        unsigned v = bins_s[bin];
        int idx = (int)(v & 0x7FFFu);
        if (v & 0x8000u) {
            while (x_s[idx] < d) ++idx;   // sentinel-terminated
        }
        float2 ab = ab_s[idx];
        return fmaf(ab.x, d, ab.y);
    };

    const long long n4 = n >> 2;
    const float4* __restrict__ in4  = (const float4*)data;
    float4* __restrict__       out4 = (float4*)out;
    const long long stride = (long long)gridDim.x * bd;
    const long long step2  = stride * 2;

    long long i = (long long)blockIdx.x * bd + tid;

    // ---- main loop: 8 elements/thread/iter, stage-structured for ILP ----
    for (; i + stride < n4; i += step2) {
        float4 v0 = in4[i];
        float4 v1 = in4[i + stride];
        float dv[8] = {v0.x, v0.y, v0.z, v0.w, v1.x, v1.y, v1.z, v1.w};
        unsigned bv[8];
        int      idxv[8];

        // stage 1: bins + bucket loads (8 independent LDS.U16)
        #pragma unroll
        for (int j = 0; j < 8; ++j) {
            float t = (dv[j] - LO) * scale;
            int bin;
            if (t < 0.0f)      bin = 0;
            else if (t >= NBf) bin = NB - 1;
            else               bin = (int)t;
            bv[j] = bins_s[bin];
        }

        // stage 2: scans (flagged lanes only; sentinel-terminated)
        #pragma unroll
        for (int j = 0; j < 8; ++j) {
            int idx = (int)(bv[j] & 0x7FFFu);
            if (bv[j] & 0x8000u) {
                while (x_s[idx] < dv[j]) ++idx;
            }
            idxv[j] = idx;
        }

        // stage 3: (a,b) gathers + FMA (8 independent LDS.64)
        float rv[8];
        #pragma unroll
        for (int j = 0; j < 8; ++j) {
            float2 ab = ab_s[idxv[j]];
            rv[j] = fmaf(ab.x, dv[j], ab.y);
        }

        out4[i]          = make_float4(rv[0], rv[1], rv[2], rv[3]);
        out4[i + stride] = make_float4(rv[4], rv[5], rv[6], rv[7]);
    }

    // leftover single float4
    for (; i < n4; i += stride) {
        float4 v = in4[i];
        float4 r;
        r.x = lut1(v.x);
        r.y = lut1(v.y);
        r.z = lut1(v.z);
        r.w = lut1(v.w);
        out4[i] = r;
    }

    // scalar tail (n not divisible by 4)
    for (long long k = (n4 << 2) + (long long)blockIdx.x * bd + tid; k < n;
         k += stride) {
        out[k] = lut1(data[k]);
    }
}

extern "C" void kernel_launch(void* const* d_in, const int* in_sizes, int n_in,
                              void* d_out, int out_size)
{
    const float* data = (const float*)d_in[0];
    const float* x    = (const float*)d_in[1];
    const float* a    = (const float*)d_in[2];
    const float* b    = (const float*)d_in[3];
    float* out        = (float*)d_out;

    int K = in_sizes[1];
    if (K > KMAX) K = KMAX;  // problem constant is 1024
    long long n = (long long)out_size;

    const int threads = 512;
    int blocks = 456;  // 3 CTAs per SM on 152 SMs
    long long need = (n / 4 + threads - 1) / threads;
    if ((long long)blocks > need && need > 0) blocks = (int)need;
    if (blocks < 1) blocks = 1;

    lut_kernel<<<blocks, threads>>>(data, x, a, b, out, K, n);
}

// round 11
// speedup vs baseline: 1.1354x; 1.0251x over previous
#include <cuda_runtime.h>
#include <cuda_bf16.h>
#include <stdint.h>

// LUT_82085414961764: out = a[idx]*d + b[idx], idx = searchsorted(x, d, 'left')
// R10: R9 (batch-8 ILP, NB=8192, 3 CTAs/SM) + 32-bit indexing (element count
// 67.1M, byte offsets < 2^31) + single-FFMA bin computation.
//   - x_s[1025]          : breakpoints + +inf sentinel (scan fallback)
//   - ab_s[1025] float2  : interleaved (a,b), single LDS.64 gather
//   - bins_s[8192] u16   : {start index (15b) | has-breakpoints flag (1b)}
// Bin function: t = fmaf(v, scale, shift) — monotone in v (scale>=0), used
// IDENTICALLY at build and query, so `start` is a provably correct lower bound.

#define KMAX 1024
#define NB   8192

__global__ __launch_bounds__(512, 3)
void lut_kernel(const float* __restrict__ data,
                const float* __restrict__ x,
                const float* __restrict__ a,
                const float* __restrict__ b,
                float* __restrict__ out,
                int K, unsigned n)
{
    __shared__ float    x_s[KMAX + 1];
    __shared__ float2   ab_s[KMAX + 1];
    __shared__ uint16_t bins_s[NB];

    const int tid = threadIdx.x;
    const int bd  = blockDim.x;

    // ---- build phase ----------------------------------------------------
    for (int i = tid; i < K; i += bd)  x_s[i] = x[i];
    for (int i = tid; i <= K; i += bd) ab_s[i] = make_float2(a[i], b[i]);
    if (tid == 0) x_s[K] = __int_as_float(0x7F800000);  // +inf sentinel
    __syncthreads();

    const float LO    = x_s[0];
    const float span  = x_s[K - 1] - LO;
    const float scale = (span > 0.0f) ? ((float)NB / span) : 0.0f;
    const float shift = -LO * scale;
    const float NBf   = (float)NB;

    // monotone bin function — identical expression at build and query
    auto g = [&](float v) -> int {
        float t = fmaf(v, scale, shift);
        if (t < 0.0f) return 0;
        if (t >= NBf) return NB - 1;
        return (int)t;
    };

    // bins_s[bin] = (first i with g(x_s[i]) >= bin) | (flag<<15)
    for (int bin = tid; bin < NB; bin += bd) {
        int lo = 0, hi = K;
        while (lo < hi) {
            int mid = (lo + hi) >> 1;
            if (g(x_s[mid]) < bin) lo = mid + 1; else hi = mid;
        }
        unsigned flag = (lo < K && g(x_s[lo]) == bin) ? 0x8000u : 0u;
        bins_s[bin] = (uint16_t)((unsigned)lo | flag);
    }
    __syncthreads();

    // single-element path (tails / odd iterations)
    auto lut1 = [&](float d) -> float {
        float t = fmaf(d, scale, shift);
        int bin;
        if (t < 0.0f)      bin = 0;
        else if (t >= NBf) bin = NB - 1;
        else               bin = (int)t;
        unsigned v = bins_s[bin];
        int idx = (int)(v & 0x7FFFu);
        if (v & 0x8000u) {
            while (x_s[idx] < d) ++idx;   // sentinel-terminated
        }
        float2 ab = ab_s[idx];
        return fmaf(ab.x, d, ab.y);
    };

    const unsigned n4 = n >> 2;              // 16.8M — fits unsigned
    const float4* __restrict__ in4  = (const float4*)data;
    float4* __restrict__       out4 = (float4*)out;
    const unsigned stride = (unsigned)gridDim.x * (unsigned)bd;
    const unsigned step2  = stride * 2u;

    unsigned i = (unsigned)blockIdx.x * (unsigned)bd + (unsigned)tid;

    // ---- main loop: 8 elements/thread/iter, stage-structured for ILP ----
    for (; i + stride < n4; i += step2) {
        float4 v0 = in4[i];
        float4 v1 = in4[i + stride];
        float dv[8] = {v0.x, v0.y, v0.z, v0.w, v1.x, v1.y, v1.z, v1.w};
        unsigned bv[8];
        int      idxv[8];

        // stage 1: bins + bucket loads (8 independent LDS.U16)
        #pragma unroll
        for (int j = 0; j < 8; ++j) {
            float t = fmaf(dv[j], scale, shift);
            int bin;
            if (t < 0.0f)      bin = 0;
            else if (t >= NBf) bin = NB - 1;
            else               bin = (int)t;
            bv[j] = bins_s[bin];
        }

        // stage 2: scans (flagged lanes only; sentinel-terminated)
        #pragma unroll
        for (int j = 0; j < 8; ++j) {
            int idx = (int)(bv[j] & 0x7FFFu);
            if (bv[j] & 0x8000u) {
                while (x_s[idx] < dv[j]) ++idx;
            }
            idxv[j] = idx;
        }

        // stage 3: (a,b) gathers + FMA (8 independent LDS.64)
        float rv[8];
        #pragma unroll
        for (int j = 0; j < 8; ++j) {
            float2 ab = ab_s[idxv[j]];
            rv[j] = fmaf(ab.x, dv[j], ab.y);
        }

        out4[i]          = make_float4(rv[0], rv[1], rv[2], rv[3]);
        out4[i + stride] = make_float4(rv[4], rv[5], rv[6], rv[7]);
    }

    // leftover single float4
    for (; i < n4; i += stride) {
        float4 v = in4[i];
        float4 r;
        r.x = lut1(v.x);
        r.y = lut1(v.y);
        r.z = lut1(v.z);
        r.w = lut1(v.w);
        out4[i] = r;
    }

    // scalar tail (n not divisible by 4)
    for (unsigned k = (n4 << 2) + (unsigned)blockIdx.x * (unsigned)bd + (unsigned)tid;
         k < n; k += stride) {
        out[k] = lut1(data[k]);
    }
}

extern "C" void kernel_launch(void* const* d_in, const int* in_sizes, int n_in,
                              void* d_out, int out_size)
{
    const float* data = (const float*)d_in[0];
    const float* x    = (const float*)d_in[1];
    const float* a    = (const float*)d_in[2];
    const float* b    = (const float*)d_in[3];
    float* out        = (float*)d_out;

    int K = in_sizes[1];
    if (K > KMAX) K = KMAX;  // problem constant is 1024
    unsigned n = (unsigned)out_size;

    const int threads = 512;
    int blocks = 456;  // 3 CTAs per SM on 152 SMs
    long long need = ((long long)n / 4 + threads - 1) / threads;
    if ((long long)blocks > need && need > 0) blocks = (int)need;
    if (blocks < 1) blocks = 1;

    lut_kernel<<<blocks, threads>>>(data, x, a, b, out, K, n);
}

// round 14
// speedup vs baseline: 1.1356x; 1.0002x over previous
#include <cuda_runtime.h>
#include <cuda_bf16.h>
#include <stdint.h>

// LUT_82085414961764: out = a[idx]*d + b[idx], idx = searchsorted(x, d, 'left')
// R11: fused-bin table (R5 idea) at NB=4096 so it fits 4 CTAs/SM (64 warps),
// batch-4 stage-structured ILP, 32-bit indexing, FFMA bin function.
//   fused[4096] float2 : empty bin  -> (a[lo], b[lo])   : one LDS.64, done
//                        flagged    -> e.x = 0x7F800000|lo (Inf-exponent tag)
//   x_s[1025]          : breakpoints + +inf sentinel (scan fallback)
//   ab_s[1025] float2  : coefficient gather for flagged lanes
// Bin function t = fmaf(v, scale, shift) is monotone (scale>=0) and IDENTICAL
// at build and query, so `lo` is a provably correct lower bound for the scan.
// Tag check (exp==255) can't collide: a,b are finite random normals.

#define KMAX 1024
#define NB   4096

__global__ __launch_bounds__(512, 4)
void lut_kernel(const float* __restrict__ data,
                const float* __restrict__ x,
                const float* __restrict__ a,
                const float* __restrict__ b,
                float* __restrict__ out,
                int K, unsigned n)
{
    __shared__ float2 fused[NB];
    __shared__ float  x_s[KMAX + 1];
    __shared__ float2 ab_s[KMAX + 1];

    const int tid = threadIdx.x;
    const int bd  = blockDim.x;

    // ---- build phase ----------------------------------------------------
    for (int i = tid; i < K; i += bd)  x_s[i] = x[i];
    for (int i = tid; i <= K; i += bd) ab_s[i] = make_float2(a[i], b[i]);
    if (tid == 0) x_s[K] = __int_as_float(0x7F800000);  // +inf sentinel
    __syncthreads();

    const float LO    = x_s[0];
    const float span  = x_s[K - 1] - LO;
    const float scale = (span > 0.0f) ? ((float)NB / span) : 0.0f;
    const float shift = -LO * scale;
    const float NBf   = (float)NB;

    // monotone bin function — identical expression at build and query
    auto g = [&](float v) -> int {
        float t = fmaf(v, scale, shift);
        if (t < 0.0f) return 0;
        if (t >= NBf) return NB - 1;
        return (int)t;
    };

    for (int bin = tid; bin < NB; bin += bd) {
        int lo = 0, hi = K;
        while (lo < hi) {
            int mid = (lo + hi) >> 1;
            if (g(x_s[mid]) < bin) lo = mid + 1; else hi = mid;
        }
        float2 e;
        if (lo < K && g(x_s[lo]) == bin) {
            e.x = __uint_as_float(0x7F800000u | (unsigned)lo);  // tagged
            e.y = 0.0f;
        } else {
            e = ab_s[lo];   // lo may equal K: ab_s[K] valid
        }
        fused[bin] = e;
    }
    __syncthreads();

    // single-element path (tail)
    auto lut1 = [&](float d) -> float {
        float t = fmaf(d, scale, shift);
        int bin;
        if (t < 0.0f)      bin = 0;
        else if (t >= NBf) bin = NB - 1;
        else               bin = (int)t;
        float2 e = fused[bin];
        unsigned ux = __float_as_uint(e.x);
        if ((ux & 0x7F800000u) == 0x7F800000u) {
            int idx = (int)(ux & 0x7FFFu);
            while (x_s[idx] < d) ++idx;        // sentinel-terminated
            e = ab_s[idx];
        }
        return fmaf(e.x, d, e.y);
    };

    const unsigned n4 = n >> 2;
    const float4* __restrict__ in4  = (const float4*)data;
    float4* __restrict__       out4 = (float4*)out;
    const unsigned stride = (unsigned)gridDim.x * (unsigned)bd;

    // ---- main loop: one float4 per thread per iter, stage-structured ----
    for (unsigned i = (unsigned)blockIdx.x * (unsigned)bd + (unsigned)tid;
         i < n4; i += stride) {
        float4 v = in4[i];
        float dv[4] = {v.x, v.y, v.z, v.w};
        float2 ev[4];

        // stage 1: bins + fused loads (4 independent LDS.64)
        #pragma unroll
        for (int j = 0; j < 4; ++j) {
            float t = fmaf(dv[j], scale, shift);
            int bin;
            if (t < 0.0f)      bin = 0;
            else if (t >= NBf) bin = NB - 1;
            else               bin = (int)t;
            ev[j] = fused[bin];
        }

        // stage 2: flagged lanes: scan + coefficient gather
        #pragma unroll
        for (int j = 0; j < 4; ++j) {
            unsigned ux = __float_as_uint(ev[j].x);
            if ((ux & 0x7F800000u) == 0x7F800000u) {
                int idx = (int)(ux & 0x7FFFu);
                while (x_s[idx] < dv[j]) ++idx;
                ev[j] = ab_s[idx];
            }
        }

        // stage 3: FMA + store
        float4 r;
        r.x = fmaf(ev[0].x, dv[0], ev[0].y);
        r.y = fmaf(ev[1].x, dv[1], ev[1].y);
        r.z = fmaf(ev[2].x, dv[2], ev[2].y);
        r.w = fmaf(ev[3].x, dv[3], ev[3].y);
        out4[i] = r;
    }

    // scalar tail (n not divisible by 4)
    for (unsigned k = (n4 << 2) + (unsigned)blockIdx.x * (unsigned)bd + (unsigned)tid;
         k < n; k += stride) {
        out[k] = lut1(data[k]);
    }
}

extern "C" void kernel_launch(void* const* d_in, const int* in_sizes, int n_in,
                              void* d_out, int out_size)
{
    const float* data = (const float*)d_in[0];
    const float* x    = (const float*)d_in[1];
    const float* a    = (const float*)d_in[2];
    const float* b    = (const float*)d_in[3];
    float* out        = (float*)d_out;

    int K = in_sizes[1];
    if (K > KMAX) K = KMAX;  // problem constant is 1024
    unsigned n = (unsigned)out_size;

    const int threads = 512;
    int blocks = 608;  // 4 CTAs per SM on 152 SMs
    long long need = ((long long)n / 4 + threads - 1) / threads;
    if ((long long)blocks > need && need > 0) blocks = (int)need;
    if (blocks < 1) blocks = 1;

    lut_kernel<<<blocks, threads>>>(data, x, a, b, out, K, n);
}